// round 2
// baseline (speedup 1.0000x reference)
#include <cuda_runtime.h>
#include <math.h>

// Problem constants
#define BATCH  4
#define NSEQ   2048
#define DMODEL 1024
#define NH     16
#define DKH    64
#define NEGV   -100000000000.0f

#define QKV_ELEMS (BATCH*NH*NSEQ*DKH)   // 8,388,608 floats = 32 MB

// Scratch (device globals; no allocation per harness rules)
__device__ float g_q[QKV_ELEMS];
__device__ float g_k[QKV_ELEMS];
__device__ float g_v[QKV_ELEMS];
__device__ float g_attn[QKV_ELEMS];

// ---------------------------------------------------------------------------
// Kernel 1: fused QKV projection GEMM.
//   C(8192x1024) = X(8192x1024) @ W(1024x1024) + bias, stored head-split:
//   out[((b*NH + h)*NSEQ + n)*DKH + dk],  row = b*NSEQ + n, col = h*64 + dk.
// 128x128 block tile, BK=8, 256 threads, 8x8 per thread (cols split 4+4 at
// stride 64 for conflict-free Bs float4 reads). blockIdx.z selects q/k/v.
// ---------------------------------------------------------------------------
__global__ __launch_bounds__(256) void proj_gemm_kernel(
    const float* __restrict__ Xq, const float* __restrict__ Xk, const float* __restrict__ Xv,
    const float* __restrict__ Wq, const float* __restrict__ Wk, const float* __restrict__ Wv,
    const float* __restrict__ bq, const float* __restrict__ bk, const float* __restrict__ bv)
{
    const int which = blockIdx.z;
    const float* __restrict__ X    = (which == 0) ? Xq : (which == 1) ? Xk : Xv;
    const float* __restrict__ W    = (which == 0) ? Wq : (which == 1) ? Wk : Wv;
    const float* __restrict__ bias = (which == 0) ? bq : (which == 1) ? bk : bv;
    float* __restrict__ out        = (which == 0) ? g_q : (which == 1) ? g_k : g_v;

    __shared__ __align__(16) float As[8][128];
    __shared__ __align__(16) float Bs[8][128];

    const int tid  = threadIdx.x;
    const int brow = blockIdx.y * 128;
    const int bcol = blockIdx.x * 128;

    const int a_row = tid >> 1;          // 0..127
    const int a_col = (tid & 1) << 2;    // 0 or 4
    const int b_row = tid >> 5;          // 0..7
    const int b_col = (tid & 31) << 2;   // 0..124

    const int ty = tid >> 4;             // 0..15  -> rows ty*8..+7
    const int tx = tid & 15;             // 0..15  -> cols tx*4..+3 and 64+tx*4..+3

    float acc[8][8];
    #pragma unroll
    for (int i = 0; i < 8; i++)
        #pragma unroll
        for (int j = 0; j < 8; j++) acc[i][j] = 0.f;

    for (int k0 = 0; k0 < DMODEL; k0 += 8) {
        float4 av = *(const float4*)(X + (size_t)(brow + a_row) * DMODEL + k0 + a_col);
        As[a_col + 0][a_row] = av.x;
        As[a_col + 1][a_row] = av.y;
        As[a_col + 2][a_row] = av.z;
        As[a_col + 3][a_row] = av.w;
        *(float4*)&Bs[b_row][b_col] =
            *(const float4*)(W + (size_t)(k0 + b_row) * DMODEL + bcol + b_col);
        __syncthreads();

        #pragma unroll
        for (int k = 0; k < 8; k++) {
            float4 a0 = *(const float4*)&As[k][ty * 8];
            float4 a1 = *(const float4*)&As[k][ty * 8 + 4];
            float4 b0 = *(const float4*)&Bs[k][tx * 4];
            float4 b1 = *(const float4*)&Bs[k][tx * 4 + 64];
            float ar[8] = {a0.x, a0.y, a0.z, a0.w, a1.x, a1.y, a1.z, a1.w};
            float br[8] = {b0.x, b0.y, b0.z, b0.w, b1.x, b1.y, b1.z, b1.w};
            #pragma unroll
            for (int i = 0; i < 8; i++)
                #pragma unroll
                for (int j = 0; j < 8; j++) acc[i][j] += ar[i] * br[j];
        }
        __syncthreads();
    }

    // Epilogue: bias + head-split store
    #pragma unroll
    for (int i = 0; i < 8; i++) {
        const int row = brow + ty * 8 + i;
        const int b   = row >> 11;            // row / NSEQ
        const int n   = row & (NSEQ - 1);
        #pragma unroll
        for (int jh = 0; jh < 2; jh++) {
            #pragma unroll
            for (int jj = 0; jj < 4; jj++) {
                const int col = bcol + jh * 64 + tx * 4 + jj;
                const int h   = col >> 6;
                const int dk  = col & 63;
                out[(((size_t)(b * NH + h) * NSEQ) + n) * DKH + dk] =
                    acc[i][jh * 4 + jj] + bias[col];
            }
        }
    }
}

// ---------------------------------------------------------------------------
// Kernel 2: flash attention. One block per (b*H, 64-query tile).
// 256 threads = 8 warps; warp w owns query rows w*8..w*8+7; lane owns output
// dims {lane, lane+32}. Online softmax, P tile reuses the K smem buffer.
// Q is pre-scaled by 1/sqrt(d_k)=0.125. smem = 3*16KB = 48KB (static).
// ---------------------------------------------------------------------------
__global__ __launch_bounds__(256) void flash_attn_kernel(const int* __restrict__ mask)
{
    __shared__ __align__(16) float Qs[64][64];
    __shared__ __align__(16) float KPs[64][64];  // K (xor-swizzled), then P (plain)
    __shared__ __align__(16) float Vs[64][64];

    const int bh   = blockIdx.y;       // 0..63
    const int b    = bh >> 4;          // / NH
    const int qt   = blockIdx.x;       // 0..31
    const int tid  = threadIdx.x;
    const int warp = tid >> 5;
    const int lane = tid & 31;
    const int r0   = warp * 8;

    // Load Q tile (pre-scaled)
    {
        const float* qptr = g_q + ((size_t)bh * NSEQ + qt * 64) * DKH;
        for (int i = tid; i < 64 * 16; i += 256) {
            const int r = i >> 4, g = i & 15;
            float4 q = *(const float4*)(qptr + r * 64 + g * 4);
            q.x *= 0.125f; q.y *= 0.125f; q.z *= 0.125f; q.w *= 0.125f;
            *(float4*)&Qs[r][g * 4] = q;
        }
    }

    float m[8], l[8], o0[8], o1[8];
    #pragma unroll
    for (int i = 0; i < 8; i++) { m[i] = -INFINITY; l[i] = 0.f; o0[i] = 0.f; o1[i] = 0.f; }

    const int* mbase = mask + ((size_t)b * NSEQ + qt * 64 + r0) * NSEQ;

    for (int kt = 0; kt < NSEQ / 64; kt++) {
        __syncthreads();   // previous tile's P/V reads done before overwrite
        {
            const float* kptr = g_k + ((size_t)bh * NSEQ + kt * 64) * DKH;
            const float* vptr = g_v + ((size_t)bh * NSEQ + kt * 64) * DKH;
            for (int i = tid; i < 64 * 16; i += 256) {
                const int r = i >> 4, g = i & 15;
                *(float4*)&KPs[r][((g ^ (r & 7)) << 2)] = *(const float4*)(kptr + r * 64 + g * 4);
                *(float4*)&Vs[r][g << 2]                = *(const float4*)(vptr + r * 64 + g * 4);
            }
        }
        __syncthreads();

        // S = Q @ K^T   (lane owns key columns {lane, lane+32})
        float s0[8], s1[8];
        #pragma unroll
        for (int i = 0; i < 8; i++) { s0[i] = 0.f; s1[i] = 0.f; }
        const int sw = (lane & 7);
        #pragma unroll 4
        for (int d4 = 0; d4 < 64; d4 += 4) {
            const int gi = ((d4 >> 2) ^ sw) << 2;
            const float4 k0 = *(const float4*)&KPs[lane][gi];
            const float4 k1 = *(const float4*)&KPs[lane + 32][gi];
            #pragma unroll
            for (int i = 0; i < 8; i++) {
                const float4 q = *(const float4*)&Qs[r0 + i][d4];
                s0[i] += q.x * k0.x; s0[i] += q.y * k0.y; s0[i] += q.z * k0.z; s0[i] += q.w * k0.w;
                s1[i] += q.x * k1.x; s1[i] += q.y * k1.y; s1[i] += q.z * k1.z; s1[i] += q.w * k1.w;
            }
        }

        // mask (coalesced int loads)
        {
            const int* mrow = mbase + kt * 64;
            #pragma unroll
            for (int i = 0; i < 8; i++) {
                const int mk0 = mrow[(size_t)i * NSEQ + lane];
                const int mk1 = mrow[(size_t)i * NSEQ + lane + 32];
                if (mk0 == 0) s0[i] = NEGV;
                if (mk1 == 0) s1[i] = NEGV;
            }
        }

        __syncthreads();   // all warps done reading K before P overwrites it

        // online softmax + write P into KPs (plain layout, warp-local rows)
        #pragma unroll
        for (int i = 0; i < 8; i++) {
            float t = fmaxf(s0[i], s1[i]);
            #pragma unroll
            for (int off = 16; off; off >>= 1)
                t = fmaxf(t, __shfl_xor_sync(0xffffffffu, t, off));
            const float mnew = fmaxf(m[i], t);
            const float p0 = __expf(s0[i] - mnew);
            const float p1 = __expf(s1[i] - mnew);
            float rs = p0 + p1;
            #pragma unroll
            for (int off = 16; off; off >>= 1)
                rs += __shfl_xor_sync(0xffffffffu, rs, off);
            const float corr = __expf(m[i] - mnew);
            l[i] = l[i] * corr + rs;
            m[i] = mnew;
            o0[i] *= corr; o1[i] *= corr;
            KPs[r0 + i][lane]      = p0;
            KPs[r0 + i][lane + 32] = p1;
        }
        __syncwarp();

        // O += P @ V   (P broadcast float4 reads; Vs[j][lane] conflict-free)
        #pragma unroll 4
        for (int j4 = 0; j4 < 64; j4 += 4) {
            const float va0 = Vs[j4 + 0][lane],      vb0 = Vs[j4 + 0][lane + 32];
            const float va1 = Vs[j4 + 1][lane],      vb1 = Vs[j4 + 1][lane + 32];
            const float va2 = Vs[j4 + 2][lane],      vb2 = Vs[j4 + 2][lane + 32];
            const float va3 = Vs[j4 + 3][lane],      vb3 = Vs[j4 + 3][lane + 32];
            #pragma unroll
            for (int i = 0; i < 8; i++) {
                const float4 p = *(const float4*)&KPs[r0 + i][j4];
                o0[i] += p.x * va0; o0[i] += p.y * va1; o0[i] += p.z * va2; o0[i] += p.w * va3;
                o1[i] += p.x * vb0; o1[i] += p.y * vb1; o1[i] += p.z * vb2; o1[i] += p.w * vb3;
            }
        }
    }

    // normalize + store head-split attention output
    float* optr = g_attn + ((size_t)bh * NSEQ + qt * 64 + r0) * DKH;
    #pragma unroll
    for (int i = 0; i < 8; i++) {
        const float inv = 1.f / l[i];
        optr[(size_t)i * DKH + lane]      = o0[i] * inv;
        optr[(size_t)i * DKH + lane + 32] = o1[i] * inv;
    }
}

// ---------------------------------------------------------------------------
// Kernel 3: output projection GEMM with gathered A (head-split -> row-major).
//   out(8192x1024) = A(8192x1024) @ Wo(1024x1024) + bo
//   A[row, k] = g_attn[((b*NH + k/64)*NSEQ + n)*DKH + k%64], row = b*NSEQ+n.
// ---------------------------------------------------------------------------
__global__ __launch_bounds__(256) void outproj_gemm_kernel(
    const float* __restrict__ W, const float* __restrict__ bias,
    float* __restrict__ out)
{
    __shared__ __align__(16) float As[8][128];
    __shared__ __align__(16) float Bs[8][128];

    const int tid  = threadIdx.x;
    const int brow = blockIdx.y * 128;
    const int bcol = blockIdx.x * 128;

    const int a_row = tid >> 1;
    const int a_col = (tid & 1) << 2;
    const int b_row = tid >> 5;
    const int b_col = (tid & 31) << 2;
    const int ty = tid >> 4;
    const int tx = tid & 15;

    const int arow_g = brow + a_row;
    const int ab = arow_g >> 11;
    const int an = arow_g & (NSEQ - 1);

    float acc[8][8];
    #pragma unroll
    for (int i = 0; i < 8; i++)
        #pragma unroll
        for (int j = 0; j < 8; j++) acc[i][j] = 0.f;

    for (int k0 = 0; k0 < DMODEL; k0 += 8) {
        const int k  = k0 + a_col;          // multiple of 4; 4 elems stay in one head
        const int h  = k >> 6;
        const int dk = k & 63;
        float4 av = *(const float4*)(g_attn +
            ((size_t)(ab * NH + h) * NSEQ + an) * DKH + dk);
        As[a_col + 0][a_row] = av.x;
        As[a_col + 1][a_row] = av.y;
        As[a_col + 2][a_row] = av.z;
        As[a_col + 3][a_row] = av.w;
        *(float4*)&Bs[b_row][b_col] =
            *(const float4*)(W + (size_t)(k0 + b_row) * DMODEL + bcol + b_col);
        __syncthreads();

        #pragma unroll
        for (int kk = 0; kk < 8; kk++) {
            float4 a0 = *(const float4*)&As[kk][ty * 8];
            float4 a1 = *(const float4*)&As[kk][ty * 8 + 4];
            float4 b0 = *(const float4*)&Bs[kk][tx * 4];
            float4 b1 = *(const float4*)&Bs[kk][tx * 4 + 64];
            float ar[8] = {a0.x, a0.y, a0.z, a0.w, a1.x, a1.y, a1.z, a1.w};
            float br[8] = {b0.x, b0.y, b0.z, b0.w, b1.x, b1.y, b1.z, b1.w};
            #pragma unroll
            for (int i = 0; i < 8; i++)
                #pragma unroll
                for (int j = 0; j < 8; j++) acc[i][j] += ar[i] * br[j];
        }
        __syncthreads();
    }

    #pragma unroll
    for (int i = 0; i < 8; i++) {
        const int row = brow + ty * 8 + i;
        #pragma unroll
        for (int jh = 0; jh < 2; jh++) {
            #pragma unroll
            for (int jj = 0; jj < 4; jj++) {
                const int col = bcol + jh * 64 + tx * 4 + jj;
                out[(size_t)row * DMODEL + col] = acc[i][jh * 4 + jj] + bias[col];
            }
        }
    }
}

// ---------------------------------------------------------------------------
extern "C" void kernel_launch(void* const* d_in, const int* in_sizes, int n_in,
                              void* d_out, int out_size)
{
    const float* query = (const float*)d_in[0];
    const float* key   = (const float*)d_in[1];
    const float* value = (const float*)d_in[2];
    const int*   mask  = (const int*)  d_in[3];
    const float* Wq    = (const float*)d_in[4];
    const float* bq    = (const float*)d_in[5];
    const float* Wk    = (const float*)d_in[6];
    const float* bk    = (const float*)d_in[7];
    const float* Wv    = (const float*)d_in[8];
    const float* bv    = (const float*)d_in[9];
    const float* Wo    = (const float*)d_in[10];
    const float* bo    = (const float*)d_in[11];
    float* out = (float*)d_out;

    dim3 gproj(DMODEL / 128, (BATCH * NSEQ) / 128, 3);   // (8, 64, 3)
    proj_gemm_kernel<<<gproj, 256>>>(query, key, value, Wq, Wk, Wv, bq, bk, bv);

    dim3 gattn(NSEQ / 64, BATCH * NH);                   // (32, 64)
    flash_attn_kernel<<<gattn, 256>>>(mask);

    dim3 gout(DMODEL / 128, (BATCH * NSEQ) / 128);       // (8, 64)
    outproj_gemm_kernel<<<gout, 256>>>(Wo, bo, out);
}

// round 5
// speedup vs baseline: 1.3579x; 1.3579x over previous
#include <cuda_runtime.h>
#include <math.h>
#include <cstdint>

// Problem constants
#define BATCH  4
#define NSEQ   2048
#define DMODEL 1024
#define NH     16
#define DKH    64
#define NEGV   -100000000000.0f

#define QKV_ELEMS (BATCH*NH*NSEQ*DKH)   // 8,388,608 floats = 32 MB

// GEMM tile config (tf32 mma.sync)
#define BM 128
#define BN 128
#define BKC 32                       // k-chunk
#define KCHUNKS (DMODEL / BKC)       // 32
#define STRIDE 36                    // smem row stride in floats (144B: 16B-aligned, conflict-free)
#define TILE_FLOATS (128 * STRIDE)   // per operand tile
#define DSMEM_BYTES (4 * TILE_FLOATS * 4)   // A0 B0 A1 B1 = 73728 B

// Scratch (device globals; no allocation per harness rules)
__device__ float g_q[QKV_ELEMS];
__device__ float g_k[QKV_ELEMS];
__device__ float g_v[QKV_ELEMS];
__device__ float g_attn[QKV_ELEMS];
__device__ float g_wt[4 * DMODEL * DMODEL];   // transposed weights (n-major)

// ---------------------------------------------------------------------------
// helpers
// ---------------------------------------------------------------------------
__device__ __forceinline__ uint32_t smem_u32(const void* p) {
    uint32_t a;
    asm("{ .reg .u64 t; cvta.to.shared.u64 t, %1; cvt.u32.u64 %0, t; }"
        : "=r"(a) : "l"(p));
    return a;
}
__device__ __forceinline__ uint32_t f2tf32(float f) {
    uint32_t u;
    asm("cvt.rna.tf32.f32 %0, %1;" : "=r"(u) : "f"(f));
    return u;
}
__device__ __forceinline__ void cp16(uint32_t dst, const void* src) {
    asm volatile("cp.async.cg.shared.global [%0], [%1], 16;" :: "r"(dst), "l"(src));
}
#define CP_COMMIT() asm volatile("cp.async.commit_group;" ::: "memory")
#define CP_WAIT0()  asm volatile("cp.async.wait_group 0;" ::: "memory")

__device__ __forceinline__ void mma_tf32(float* c, const uint32_t* a, const uint32_t* b) {
    asm volatile(
        "mma.sync.aligned.m16n8k8.row.col.f32.tf32.tf32.f32 "
        "{%0,%1,%2,%3}, {%4,%5,%6,%7}, {%8,%9}, {%0,%1,%2,%3};"
        : "+f"(c[0]), "+f"(c[1]), "+f"(c[2]), "+f"(c[3])
        : "r"(a[0]), "r"(a[1]), "r"(a[2]), "r"(a[3]), "r"(b[0]), "r"(b[1]));
}

// ---------------------------------------------------------------------------
// Kernel 0: transpose the 4 weight matrices into g_wt (WT[n][k] = W[k][n]).
// ---------------------------------------------------------------------------
__global__ __launch_bounds__(256) void transpose4_kernel(
    const float* __restrict__ Wq, const float* __restrict__ Wk,
    const float* __restrict__ Wv, const float* __restrict__ Wo)
{
    __shared__ float t[32][33];
    const int z = blockIdx.z;
    const float* W = (z == 0) ? Wq : (z == 1) ? Wk : (z == 2) ? Wv : Wo;
    float* WT = g_wt + (size_t)z * DMODEL * DMODEL;

    const int tx = threadIdx.x, ty = threadIdx.y;
    const int x = blockIdx.x * 32 + tx;
    const int y0 = blockIdx.y * 32;
    #pragma unroll
    for (int i = ty; i < 32; i += 8)
        t[i][tx] = W[(size_t)(y0 + i) * DMODEL + x];
    __syncthreads();
    const int k = blockIdx.y * 32 + tx;
    #pragma unroll
    for (int i = ty; i < 32; i += 8)
        WT[(size_t)(blockIdx.x * 32 + i) * DMODEL + k] = t[tx][i];
}

// ---------------------------------------------------------------------------
// cp.async tile loaders: 256 threads, 128 rows x 32 floats per tile (8 x 16B).
// ---------------------------------------------------------------------------
__device__ __forceinline__ void cp_tile(float* sm, const float* __restrict__ g,
                                        int k0, int tid)
{
    #pragma unroll
    for (int i = 0; i < 4; i++) {
        const int flat = i * 256 + tid;
        const int r = flat >> 3, seg = flat & 7;
        cp16(smem_u32(sm + r * STRIDE + seg * 4),
             g + (size_t)r * DMODEL + k0 + seg * 4);
    }
}
// Gathered A tile from head-split g_attn
__device__ __forceinline__ void cp_tile_gather(float* sm, int brow, int k0, int tid)
{
    #pragma unroll
    for (int i = 0; i < 4; i++) {
        const int flat = i * 256 + tid;
        const int r = flat >> 3, seg = flat & 7;
        const int row = brow + r;
        const int bi = row >> 11, n = row & (NSEQ - 1);
        const int k = k0 + seg * 4;
        const int h = k >> 6, dk = k & 63;
        cp16(smem_u32(sm + r * STRIDE + seg * 4),
             g_attn + ((size_t)(bi * NH + h) * NSEQ + n) * DKH + dk);
    }
}

// ---------------------------------------------------------------------------
// Core mma compute for one k-chunk (BKC=32 -> 4 ksteps of 8).
// As: [BM][STRIDE] row-major (m,k). Bs: [BN][STRIDE] (n,k).
// Warp tile 32(m) x 64(n): 2 m-tiles x 8 n-tiles of m16n8k8.
// ---------------------------------------------------------------------------
__device__ __forceinline__ void compute_chunk(const float* As, const float* Bs,
                                              float acc[2][8][4], int wm, int wn, int lane)
{
    const int gr = lane >> 2, gc = lane & 3;
    #pragma unroll
    for (int ks = 0; ks < 4; ks++) {
        const int kk = ks * 8 + gc;
        uint32_t af[2][4];
        #pragma unroll
        for (int mt = 0; mt < 2; mt++) {
            const int r = wm + mt * 16 + gr;
            af[mt][0] = f2tf32(As[r * STRIDE + kk]);
            af[mt][1] = f2tf32(As[(r + 8) * STRIDE + kk]);
            af[mt][2] = f2tf32(As[r * STRIDE + kk + 4]);
            af[mt][3] = f2tf32(As[(r + 8) * STRIDE + kk + 4]);
        }
        uint32_t bf[8][2];
        #pragma unroll
        for (int nt = 0; nt < 8; nt++) {
            const int nn = wn + nt * 8 + gr;
            bf[nt][0] = f2tf32(Bs[nn * STRIDE + kk]);
            bf[nt][1] = f2tf32(Bs[nn * STRIDE + kk + 4]);
        }
        #pragma unroll
        for (int mt = 0; mt < 2; mt++)
            #pragma unroll
            for (int nt = 0; nt < 8; nt++)
                mma_tf32(acc[mt][nt], af[mt], bf[nt]);
    }
}

// ---------------------------------------------------------------------------
// Kernel 1: QKV projection, tf32 mma.sync, double-buffered cp.async.
// Output head-split into g_q/g_k/g_v.
// ---------------------------------------------------------------------------
__global__ __launch_bounds__(256) void proj_mma_kernel(
    const float* __restrict__ Xq, const float* __restrict__ Xk, const float* __restrict__ Xv,
    const float* __restrict__ bq, const float* __restrict__ bk, const float* __restrict__ bv)
{
    extern __shared__ float dsm[];
    float* Abuf[2] = { dsm,                  dsm + 2 * TILE_FLOATS };
    float* Bbuf[2] = { dsm + TILE_FLOATS,    dsm + 3 * TILE_FLOATS };

    const int which = blockIdx.z;
    const float* __restrict__ X    = (which == 0) ? Xq : (which == 1) ? Xk : Xv;
    const float* __restrict__ bias = (which == 0) ? bq : (which == 1) ? bk : bv;
    float* __restrict__ out        = (which == 0) ? g_q : (which == 1) ? g_k : g_v;
    const float* __restrict__ WT   = g_wt + (size_t)which * DMODEL * DMODEL;

    const int tid = threadIdx.x, warp = tid >> 5, lane = tid & 31;
    const int brow = blockIdx.y * BM, bcol = blockIdx.x * BN;
    const int wm = (warp & 3) * 32;      // warp row
    const int wn = (warp >> 2) * 64;     // warp col

    const float* Ag = X  + (size_t)brow * DMODEL;
    const float* Bg = WT + (size_t)bcol * DMODEL;

    float acc[2][8][4];
    #pragma unroll
    for (int mt = 0; mt < 2; mt++)
        #pragma unroll
        for (int nt = 0; nt < 8; nt++)
            #pragma unroll
            for (int i = 0; i < 4; i++) acc[mt][nt][i] = 0.f;

    cp_tile(Abuf[0], Ag, 0, tid);
    cp_tile(Bbuf[0], Bg, 0, tid);
    CP_COMMIT();

    for (int it = 0; it < KCHUNKS; ++it) {
        const int cur = it & 1;
        CP_WAIT0();
        __syncthreads();
        if (it + 1 < KCHUNKS) {
            const int nb = cur ^ 1;
            cp_tile(Abuf[nb], Ag, (it + 1) * BKC, tid);
            cp_tile(Bbuf[nb], Bg, (it + 1) * BKC, tid);
            CP_COMMIT();
        }
        compute_chunk(Abuf[cur], Bbuf[cur], acc, wm, wn, lane);
    }

    // Epilogue: bias + head-split store
    const int gr = lane >> 2, gc = lane & 3;
    #pragma unroll
    for (int mt = 0; mt < 2; mt++) {
        const int r_lo = brow + wm + mt * 16 + gr;
        #pragma unroll
        for (int half = 0; half < 2; half++) {
            const int row = r_lo + half * 8;
            const int bi = row >> 11, n = row & (NSEQ - 1);
            float* orow = out + ((size_t)bi * NH * NSEQ) * DKH + (size_t)n * DKH;
            #pragma unroll
            for (int nt = 0; nt < 8; nt++) {
                const int col = bcol + wn + nt * 8 + gc * 2;
                const int h = col >> 6, dk = col & 63;
                const float2 bv2 = *(const float2*)(bias + col);
                float2 o;
                o.x = acc[mt][nt][half * 2 + 0] + bv2.x;
                o.y = acc[mt][nt][half * 2 + 1] + bv2.y;
                *(float2*)(orow + (size_t)h * NSEQ * DKH + dk) = o;
            }
        }
    }
}

// ---------------------------------------------------------------------------
// Kernel 3: output projection, tf32 mma.sync (A gathered from head-split g_attn).
// ---------------------------------------------------------------------------
__global__ __launch_bounds__(256) void outproj_mma_kernel(
    const float* __restrict__ bias, float* __restrict__ out)
{
    extern __shared__ float dsm[];
    float* Abuf[2] = { dsm,                  dsm + 2 * TILE_FLOATS };
    float* Bbuf[2] = { dsm + TILE_FLOATS,    dsm + 3 * TILE_FLOATS };

    const float* __restrict__ WT = g_wt + (size_t)3 * DMODEL * DMODEL;

    const int tid = threadIdx.x, warp = tid >> 5, lane = tid & 31;
    const int brow = blockIdx.y * BM, bcol = blockIdx.x * BN;
    const int wm = (warp & 3) * 32;
    const int wn = (warp >> 2) * 64;

    const float* Bg = WT + (size_t)bcol * DMODEL;

    float acc[2][8][4];
    #pragma unroll
    for (int mt = 0; mt < 2; mt++)
        #pragma unroll
        for (int nt = 0; nt < 8; nt++)
            #pragma unroll
            for (int i = 0; i < 4; i++) acc[mt][nt][i] = 0.f;

    cp_tile_gather(Abuf[0], brow, 0, tid);
    cp_tile(Bbuf[0], Bg, 0, tid);
    CP_COMMIT();

    for (int it = 0; it < KCHUNKS; ++it) {
        const int cur = it & 1;
        CP_WAIT0();
        __syncthreads();
        if (it + 1 < KCHUNKS) {
            const int nb = cur ^ 1;
            cp_tile_gather(Abuf[nb], brow, (it + 1) * BKC, tid);
            cp_tile(Bbuf[nb], Bg, (it + 1) * BKC, tid);
            CP_COMMIT();
        }
        compute_chunk(Abuf[cur], Bbuf[cur], acc, wm, wn, lane);
    }

    const int gr = lane >> 2, gc = lane & 3;
    #pragma unroll
    for (int mt = 0; mt < 2; mt++) {
        const int r_lo = brow + wm + mt * 16 + gr;
        #pragma unroll
        for (int half = 0; half < 2; half++) {
            const int row = r_lo + half * 8;
            #pragma unroll
            for (int nt = 0; nt < 8; nt++) {
                const int col = bcol + wn + nt * 8 + gc * 2;
                const float2 bv2 = *(const float2*)(bias + col);
                float2 o;
                o.x = acc[mt][nt][half * 2 + 0] + bv2.x;
                o.y = acc[mt][nt][half * 2 + 1] + bv2.y;
                *(float2*)(out + (size_t)row * DMODEL + col) = o;
            }
        }
    }
}

// ---------------------------------------------------------------------------
// Kernel 2: flash attention (fp32, unchanged from the passing baseline).
// ---------------------------------------------------------------------------
__global__ __launch_bounds__(256) void flash_attn_kernel(const int* __restrict__ mask)
{
    __shared__ __align__(16) float Qs[64][64];
    __shared__ __align__(16) float KPs[64][64];
    __shared__ __align__(16) float Vs[64][64];

    const int bh   = blockIdx.y;
    const int b    = bh >> 4;
    const int qt   = blockIdx.x;
    const int tid  = threadIdx.x;
    const int warp = tid >> 5;
    const int lane = tid & 31;
    const int r0   = warp * 8;

    {
        const float* qptr = g_q + ((size_t)bh * NSEQ + qt * 64) * DKH;
        for (int i = tid; i < 64 * 16; i += 256) {
            const int r = i >> 4, g = i & 15;
            float4 q = *(const float4*)(qptr + r * 64 + g * 4);
            q.x *= 0.125f; q.y *= 0.125f; q.z *= 0.125f; q.w *= 0.125f;
            *(float4*)&Qs[r][g * 4] = q;
        }
    }

    float m[8], l[8], o0[8], o1[8];
    #pragma unroll
    for (int i = 0; i < 8; i++) { m[i] = -INFINITY; l[i] = 0.f; o0[i] = 0.f; o1[i] = 0.f; }

    const int* mbase = mask + ((size_t)b * NSEQ + qt * 64 + r0) * NSEQ;

    for (int kt = 0; kt < NSEQ / 64; kt++) {
        __syncthreads();
        {
            const float* kptr = g_k + ((size_t)bh * NSEQ + kt * 64) * DKH;
            const float* vptr = g_v + ((size_t)bh * NSEQ + kt * 64) * DKH;
            for (int i = tid; i < 64 * 16; i += 256) {
                const int r = i >> 4, g = i & 15;
                *(float4*)&KPs[r][((g ^ (r & 7)) << 2)] = *(const float4*)(kptr + r * 64 + g * 4);
                *(float4*)&Vs[r][g << 2]                = *(const float4*)(vptr + r * 64 + g * 4);
            }
        }
        __syncthreads();

        float s0[8], s1[8];
        #pragma unroll
        for (int i = 0; i < 8; i++) { s0[i] = 0.f; s1[i] = 0.f; }
        const int sw = (lane & 7);
        #pragma unroll 4
        for (int d4 = 0; d4 < 64; d4 += 4) {
            const int gi = ((d4 >> 2) ^ sw) << 2;
            const float4 k0 = *(const float4*)&KPs[lane][gi];
            const float4 k1 = *(const float4*)&KPs[lane + 32][gi];
            #pragma unroll
            for (int i = 0; i < 8; i++) {
                const float4 q = *(const float4*)&Qs[r0 + i][d4];
                s0[i] += q.x * k0.x; s0[i] += q.y * k0.y; s0[i] += q.z * k0.z; s0[i] += q.w * k0.w;
                s1[i] += q.x * k1.x; s1[i] += q.y * k1.y; s1[i] += q.z * k1.z; s1[i] += q.w * k1.w;
            }
        }

        {
            const int* mrow = mbase + kt * 64;
            #pragma unroll
            for (int i = 0; i < 8; i++) {
                const int mk0 = mrow[(size_t)i * NSEQ + lane];
                const int mk1 = mrow[(size_t)i * NSEQ + lane + 32];
                if (mk0 == 0) s0[i] = NEGV;
                if (mk1 == 0) s1[i] = NEGV;
            }
        }

        __syncthreads();

        #pragma unroll
        for (int i = 0; i < 8; i++) {
            float t = fmaxf(s0[i], s1[i]);
            #pragma unroll
            for (int off = 16; off; off >>= 1)
                t = fmaxf(t, __shfl_xor_sync(0xffffffffu, t, off));
            const float mnew = fmaxf(m[i], t);
            const float p0 = __expf(s0[i] - mnew);
            const float p1 = __expf(s1[i] - mnew);
            float rs = p0 + p1;
            #pragma unroll
            for (int off = 16; off; off >>= 1)
                rs += __shfl_xor_sync(0xffffffffu, rs, off);
            const float corr = __expf(m[i] - mnew);
            l[i] = l[i] * corr + rs;
            m[i] = mnew;
            o0[i] *= corr; o1[i] *= corr;
            KPs[r0 + i][lane]      = p0;
            KPs[r0 + i][lane + 32] = p1;
        }
        __syncwarp();

        #pragma unroll 4
        for (int j4 = 0; j4 < 64; j4 += 4) {
            const float va0 = Vs[j4 + 0][lane],      vb0 = Vs[j4 + 0][lane + 32];
            const float va1 = Vs[j4 + 1][lane],      vb1 = Vs[j4 + 1][lane + 32];
            const float va2 = Vs[j4 + 2][lane],      vb2 = Vs[j4 + 2][lane + 32];
            const float va3 = Vs[j4 + 3][lane],      vb3 = Vs[j4 + 3][lane + 32];
            #pragma unroll
            for (int i = 0; i < 8; i++) {
                const float4 p = *(const float4*)&KPs[r0 + i][j4];
                o0[i] += p.x * va0; o0[i] += p.y * va1; o0[i] += p.z * va2; o0[i] += p.w * va3;
                o1[i] += p.x * vb0; o1[i] += p.y * vb1; o1[i] += p.z * vb2; o1[i] += p.w * vb3;
            }
        }
    }

    float* optr = g_attn + ((size_t)bh * NSEQ + qt * 64 + r0) * DKH;
    #pragma unroll
    for (int i = 0; i < 8; i++) {
        const float inv = 1.f / l[i];
        optr[(size_t)i * DKH + lane]      = o0[i] * inv;
        optr[(size_t)i * DKH + lane + 32] = o1[i] * inv;
    }
}

// ---------------------------------------------------------------------------
extern "C" void kernel_launch(void* const* d_in, const int* in_sizes, int n_in,
                              void* d_out, int out_size)
{
    const float* query = (const float*)d_in[0];
    const float* key   = (const float*)d_in[1];
    const float* value = (const float*)d_in[2];
    const int*   mask  = (const int*)  d_in[3];
    const float* Wq    = (const float*)d_in[4];
    const float* bq    = (const float*)d_in[5];
    const float* Wk    = (const float*)d_in[6];
    const float* bk    = (const float*)d_in[7];
    const float* Wv    = (const float*)d_in[8];
    const float* bv    = (const float*)d_in[9];
    const float* Wo    = (const float*)d_in[10];
    const float* bo    = (const float*)d_in[11];
    float* out = (float*)d_out;

    cudaFuncSetAttribute(proj_mma_kernel,
                         cudaFuncAttributeMaxDynamicSharedMemorySize, DSMEM_BYTES);
    cudaFuncSetAttribute(outproj_mma_kernel,
                         cudaFuncAttributeMaxDynamicSharedMemorySize, DSMEM_BYTES);

    transpose4_kernel<<<dim3(32, 32, 4), dim3(32, 8)>>>(Wq, Wk, Wv, Wo);

    dim3 gproj(DMODEL / BN, (BATCH * NSEQ) / BM, 3);     // (8, 64, 3)
    proj_mma_kernel<<<gproj, 256, DSMEM_BYTES>>>(query, key, value, bq, bk, bv);

    dim3 gattn(NSEQ / 64, BATCH * NH);                   // (32, 64)
    flash_attn_kernel<<<gattn, 256>>>(mask);

    dim3 gout(DMODEL / BN, (BATCH * NSEQ) / BM);         // (8, 64)
    outproj_mma_kernel<<<gout, 256, DSMEM_BYTES>>>(bo, out);
}